// round 1
// baseline (speedup 1.0000x reference)
#include <cuda_runtime.h>
#include <cstdint>

// Problem constants
static constexpr int B_  = 8;
static constexpr int T_  = 2048;
static constexpr int C_  = 1024;
static constexpr int H_  = 16;
static constexpr int D_  = 64;      // head dim
static constexpr int TC3 = 3 * C_;  // 3072
static constexpr int M_  = B_ * T_; // 16384 rows of x

// Scratch: q,k,v in (B,H,T,D) layout, 64 MiB each (device globals: allowed)
__device__ float g_q[(size_t)B_ * H_ * T_ * D_];
__device__ float g_k[(size_t)B_ * H_ * T_ * D_];
__device__ float g_v[(size_t)B_ * H_ * T_ * D_];

// ---------------------------------------------------------------------------
// Kernel 1: qkv = x @ W_qkv + b_qkv, scattered into g_q/g_k/g_v (B,H,T,D)
// 128x128 block tile, BK=16, 256 threads, 8x8 per-thread microtile.
// ---------------------------------------------------------------------------
__global__ __launch_bounds__(256) void qkv_gemm_kernel(
    const float* __restrict__ x,      // (M_, C_)
    const float* __restrict__ W,      // (C_, TC3)
    const float* __restrict__ bias)   // (TC3,)
{
    __shared__ float As[16][132];   // transposed x tile, +4 pad keeps f4 align
    __shared__ float Bs[16][128];

    const int bm  = blockIdx.y;
    const int bn  = blockIdx.x;
    const int tid = threadIdx.x;
    const int tr  = tid >> 4;       // 0..15
    const int tc  = tid & 15;       // 0..15

    float acc[8][8];
#pragma unroll
    for (int i = 0; i < 8; ++i)
#pragma unroll
        for (int j = 0; j < 8; ++j) acc[i][j] = 0.f;

    const float* xblk = x + (size_t)bm * 128 * C_;
    const float* Wblk = W + (size_t)bn * 128;

    for (int k0 = 0; k0 < C_; k0 += 16) {
        // Load A tile (128 rows x 16 k), transpose into As[k][row]
#pragma unroll
        for (int i = 0; i < 2; ++i) {
            int f   = tid + i * 256;          // 0..511
            int row = f >> 2;                 // 0..127
            int kc  = (f & 3) << 2;           // 0,4,8,12
            float4 v = *(const float4*)(xblk + (size_t)row * C_ + k0 + kc);
            As[kc + 0][row] = v.x;
            As[kc + 1][row] = v.y;
            As[kc + 2][row] = v.z;
            As[kc + 3][row] = v.w;
        }
        // Load B tile (16 k x 128 n), row-major
#pragma unroll
        for (int i = 0; i < 2; ++i) {
            int f   = tid + i * 256;          // 0..511
            int row = f >> 5;                 // 0..15
            int c4  = (f & 31) << 2;          // 0..124
            *(float4*)(&Bs[row][c4]) =
                *(const float4*)(Wblk + (size_t)(k0 + row) * TC3 + c4);
        }
        __syncthreads();

#pragma unroll
        for (int kk = 0; kk < 16; ++kk) {
            float a[8], bb[8];
            *(float4*)(a)      = *(float4*)(&As[kk][tr * 4]);
            *(float4*)(a + 4)  = *(float4*)(&As[kk][64 + tr * 4]);
            *(float4*)(bb)     = *(float4*)(&Bs[kk][tc * 4]);
            *(float4*)(bb + 4) = *(float4*)(&Bs[kk][64 + tc * 4]);
#pragma unroll
            for (int i = 0; i < 8; ++i)
#pragma unroll
                for (int j = 0; j < 8; ++j)
                    acc[i][j] = fmaf(a[i], bb[j], acc[i][j]);
        }
        __syncthreads();
    }

    // Epilogue: add bias, scatter to q/k/v in (B,H,T,D) layout, float4 stores
#pragma unroll
    for (int ig = 0; ig < 2; ++ig) {
#pragma unroll
        for (int ii = 0; ii < 4; ++ii) {
            int rloc = ig * 64 + tr * 4 + ii;
            int m    = bm * 128 + rloc;
            int bb_i = m >> 11;           // /2048
            int tt   = m & 2047;
#pragma unroll
            for (int jg = 0; jg < 2; ++jg) {
                int cloc = jg * 64 + tc * 4;
                int n    = bn * 128 + cloc;
                int which = n >> 10;      // 0=q 1=k 2=v
                int cc    = n & 1023;
                int hh    = cc >> 6;
                int dd    = cc & 63;
                float4 bv = *(const float4*)(bias + n);
                float4 r;
                r.x = acc[ig * 4 + ii][jg * 4 + 0] + bv.x;
                r.y = acc[ig * 4 + ii][jg * 4 + 1] + bv.y;
                r.z = acc[ig * 4 + ii][jg * 4 + 2] + bv.z;
                r.w = acc[ig * 4 + ii][jg * 4 + 3] + bv.w;
                float* dst = (which == 0) ? g_q : (which == 1) ? g_k : g_v;
                *(float4*)(dst + ((size_t)(bb_i * H_ + hh) * T_ + tt) * D_ + dd) = r;
            }
        }
    }
}

// ---------------------------------------------------------------------------
// Kernel 2: flash-style attention. One CTA per (b, h, 128 q-rows).
// 256 threads as 16x16; each thread: 8 q-rows x 4 cols.
// Online softmax over K blocks of 64. All fp32.
// ---------------------------------------------------------------------------
static constexpr int AT_SMEM_FLOATS = 64 * 132 + 64 * 68 + 64 * 68 + 64 * 132;
static constexpr int AT_SMEM_BYTES  = AT_SMEM_FLOATS * 4 + 64 * 4;

__global__ __launch_bounds__(256) void attn_kernel(
    const int* __restrict__ mask,   // (B_, T_) effectively
    float* __restrict__ out)        // (B_, T_, C_) in the (B,H,T,D)-flat view
{
    extern __shared__ float sm[];
    float* Qt = sm;                       // [64 d][132]  (128 q-rows + pad)
    float* Kt = Qt + 64 * 132;            // [64 d][68]   (64 k-rows + pad)
    float* Vs = Kt + 64 * 68;             // [64 k][68]   (64 d-cols + pad)
    float* Pt = Vs + 64 * 68;             // [64 k][132]  (128 q-rows + pad)
    int*   mk = (int*)(Pt + 64 * 132);    // [64]

    const int qb  = blockIdx.x;           // 0..15 (128 q rows each)
    const int h   = blockIdx.y;
    const int b   = blockIdx.z;
    const int tid = threadIdx.x;
    const int tr  = tid >> 4;             // 0..15 -> 8 q-rows each
    const int tc  = tid & 15;             // 0..15 -> 4 cols each

    const size_t bh    = (size_t)(b * H_ + h);
    const float* qptr  = g_q + (bh * T_ + (size_t)qb * 128) * D_;
    const float* kbase = g_k + bh * T_ * D_;
    const float* vbase = g_v + bh * T_ * D_;
    const int*   mbase = mask + (size_t)b * T_;

    // Load Q tile (128 x 64) transposed: Qt[d][row]
#pragma unroll
    for (int i = 0; i < 8; ++i) {
        int f  = tid + i * 256;           // 0..2047
        int r  = f >> 4;                  // 0..127
        int c4 = (f & 15) << 2;           // 0..60
        float4 v = *(const float4*)(qptr + (size_t)r * D_ + c4);
        Qt[(c4 + 0) * 132 + r] = v.x;
        Qt[(c4 + 1) * 132 + r] = v.y;
        Qt[(c4 + 2) * 132 + r] = v.z;
        Qt[(c4 + 3) * 132 + r] = v.w;
    }

    float m_r[8], l_r[8], o[8][4];
#pragma unroll
    for (int i = 0; i < 8; ++i) {
        m_r[i] = -1e30f;
        l_r[i] = 0.f;
#pragma unroll
        for (int j = 0; j < 4; ++j) o[i][j] = 0.f;
    }

    const float scale = 0.125f;   // d^-0.5, d=64

    for (int kb = 0; kb < T_ / 64; ++kb) {
        const float* kptr = kbase + (size_t)kb * 64 * D_;
        const float* vptr = vbase + (size_t)kb * 64 * D_;
        // K tile transposed: Kt[d][krow]
#pragma unroll
        for (int i = 0; i < 4; ++i) {
            int f  = tid + i * 256;       // 0..1023
            int r  = f >> 4;              // 0..63
            int c4 = (f & 15) << 2;
            float4 v = *(const float4*)(kptr + (size_t)r * D_ + c4);
            Kt[(c4 + 0) * 68 + r] = v.x;
            Kt[(c4 + 1) * 68 + r] = v.y;
            Kt[(c4 + 2) * 68 + r] = v.z;
            Kt[(c4 + 3) * 68 + r] = v.w;
        }
        // V tile natural: Vs[krow][d]
#pragma unroll
        for (int i = 0; i < 4; ++i) {
            int f  = tid + i * 256;
            int r  = f >> 4;
            int c4 = (f & 15) << 2;
            *(float4*)(Vs + r * 68 + c4) =
                *(const float4*)(vptr + (size_t)r * D_ + c4);
        }
        if (tid < 64) mk[tid] = mbase[kb * 64 + tid];
        __syncthreads();

        // S = Q . K^T (128 x 64): each thread 8x4
        float s[8][4];
#pragma unroll
        for (int i = 0; i < 8; ++i)
#pragma unroll
            for (int j = 0; j < 4; ++j) s[i][j] = 0.f;

#pragma unroll
        for (int d = 0; d < 64; ++d) {
            float a[8], kk4[4];
            *(float4*)(a)     = *(float4*)(&Qt[d * 132 + tr * 8]);
            *(float4*)(a + 4) = *(float4*)(&Qt[d * 132 + tr * 8 + 4]);
            *(float4*)(kk4)   = *(float4*)(&Kt[d * 68 + tc * 4]);
#pragma unroll
            for (int i = 0; i < 8; ++i)
#pragma unroll
                for (int j = 0; j < 4; ++j)
                    s[i][j] = fmaf(a[i], kk4[j], s[i][j]);
        }

        // mask + scale (mask==0 -> -1e30; self-corrects via rescale)
        int mj[4];
#pragma unroll
        for (int j = 0; j < 4; ++j) mj[j] = mk[tc * 4 + j];
#pragma unroll
        for (int i = 0; i < 8; ++i)
#pragma unroll
            for (int j = 0; j < 4; ++j)
                s[i][j] = mj[j] ? s[i][j] * scale : -1e30f;

        // Online softmax per q-row (row spread across 16 lanes of half-warp)
#pragma unroll
        for (int i = 0; i < 8; ++i) {
            float rm = fmaxf(fmaxf(s[i][0], s[i][1]), fmaxf(s[i][2], s[i][3]));
#pragma unroll
            for (int st = 1; st < 16; st <<= 1)
                rm = fmaxf(rm, __shfl_xor_sync(0xffffffffu, rm, st));
            float mnew = fmaxf(m_r[i], rm);
            float corr = __expf(m_r[i] - mnew);
            m_r[i] = mnew;
            float rs = 0.f;
#pragma unroll
            for (int j = 0; j < 4; ++j) {
                float p = __expf(s[i][j] - mnew);
                s[i][j] = p;
                rs += p;
            }
#pragma unroll
            for (int st = 1; st < 16; st <<= 1)
                rs += __shfl_xor_sync(0xffffffffu, rs, st);
            l_r[i] = l_r[i] * corr + rs;
            o[i][0] *= corr; o[i][1] *= corr; o[i][2] *= corr; o[i][3] *= corr;
            // store P transposed: Pt[kcol][qrow]
#pragma unroll
            for (int j = 0; j < 4; ++j)
                Pt[(tc * 4 + j) * 132 + tr * 8 + i] = s[i][j];
        }
        __syncthreads();

        // O += P . V  (128 x 64): each thread 8x4
#pragma unroll
        for (int kk = 0; kk < 64; ++kk) {
            float p[8], v4[4];
            *(float4*)(p)     = *(float4*)(&Pt[kk * 132 + tr * 8]);
            *(float4*)(p + 4) = *(float4*)(&Pt[kk * 132 + tr * 8 + 4]);
            *(float4*)(v4)    = *(float4*)(&Vs[kk * 68 + tc * 4]);
#pragma unroll
            for (int i = 0; i < 8; ++i)
#pragma unroll
                for (int j = 0; j < 4; ++j)
                    o[i][j] = fmaf(p[i], v4[j], o[i][j]);
        }
        __syncthreads();
    }

    // Normalize and write. out index = b*T*C + h*T*D + t*D + dd
    float* obase = out + (size_t)b * T_ * C_ + (size_t)h * T_ * D_
                       + (size_t)qb * 128 * D_ + tc * 4;
#pragma unroll
    for (int i = 0; i < 8; ++i) {
        float inv = (l_r[i] > 0.f) ? (1.0f / l_r[i]) : 0.f;
        float4 r;
        r.x = o[i][0] * inv;
        r.y = o[i][1] * inv;
        r.z = o[i][2] * inv;
        r.w = o[i][3] * inv;
        *(float4*)(obase + (size_t)(tr * 8 + i) * D_) = r;
    }
}

// ---------------------------------------------------------------------------
extern "C" void kernel_launch(void* const* d_in, const int* in_sizes, int n_in,
                              void* d_out, int out_size) {
    (void)in_sizes; (void)n_in; (void)out_size;
    const float* x    = (const float*)d_in[0];
    const int*   mask = (const int*)d_in[1];
    const float* W    = (const float*)d_in[2];
    const float* bias = (const float*)d_in[3];
    float*       out  = (float*)d_out;

    // One-time opt-in to >48KB dynamic smem (runs on first call, pre-capture)
    static int _attr_once = []() {
        cudaFuncSetAttribute(attn_kernel,
                             cudaFuncAttributeMaxDynamicSharedMemorySize,
                             AT_SMEM_BYTES);
        return 0;
    }();
    (void)_attr_once;

    dim3 g1(TC3 / 128, M_ / 128);   // (24, 128)
    qkv_gemm_kernel<<<g1, 256>>>(x, W, bias);

    dim3 g2(T_ / 128, H_, B_);      // (16, 16, 8)
    attn_kernel<<<g2, 256, AT_SMEM_BYTES>>>(mask, out);
}

// round 2
// speedup vs baseline: 1.6535x; 1.6535x over previous
#include <cuda_runtime.h>
#include <cstdint>

// Problem constants
static constexpr int B_  = 8;
static constexpr int T_  = 2048;
static constexpr int C_  = 1024;
static constexpr int H_  = 16;
static constexpr int D_  = 64;
static constexpr int TC3 = 3 * C_;   // 3072
static constexpr int M_  = B_ * T_;  // 16384

// Scratch q,k,v in (B,H,T,D) layout (device globals: allowed)
__device__ float g_q[(size_t)B_ * H_ * T_ * D_];
__device__ float g_k[(size_t)B_ * H_ * T_ * D_];
__device__ float g_v[(size_t)B_ * H_ * T_ * D_];

// ---------------------------------------------------------------------------
// PTX helpers
// ---------------------------------------------------------------------------
__device__ __forceinline__ uint32_t f2tf(float f) {
    uint32_t u;
    asm("cvt.rna.tf32.f32 %0, %1;" : "=r"(u) : "f"(f));
    return u;
}
__device__ __forceinline__ uint32_t sptr(const void* p) {
    return (uint32_t)__cvta_generic_to_shared(p);
}
__device__ __forceinline__ void ldsm4(uint32_t& r0, uint32_t& r1,
                                      uint32_t& r2, uint32_t& r3, uint32_t a) {
    asm volatile("ldmatrix.sync.aligned.m8n8.x4.shared.b16 {%0,%1,%2,%3}, [%4];"
                 : "=r"(r0), "=r"(r1), "=r"(r2), "=r"(r3) : "r"(a));
}
__device__ __forceinline__ void mma_tf32(float* d, const uint32_t* a,
                                         const uint32_t* b) {
    asm volatile(
        "mma.sync.aligned.m16n8k8.row.col.f32.tf32.tf32.f32 "
        "{%0,%1,%2,%3}, {%4,%5,%6,%7}, {%8,%9}, {%0,%1,%2,%3};"
        : "+f"(d[0]), "+f"(d[1]), "+f"(d[2]), "+f"(d[3])
        : "r"(a[0]), "r"(a[1]), "r"(a[2]), "r"(a[3]), "r"(b[0]), "r"(b[1]));
}

// ---------------------------------------------------------------------------
// Kernel 1: qkv = x @ W + b, tf32 mma, scatter to g_q/g_k/g_v (B,H,T,D)
// 128x128x16 tile, 8 warps (2M x 4N), warp tile 64x32.
// ---------------------------------------------------------------------------
__global__ __launch_bounds__(256) void qkv_gemm_kernel(
    const float* __restrict__ x,      // (M_, C_)
    const float* __restrict__ W,      // (C_, TC3)
    const float* __restrict__ bias)   // (TC3,)
{
    __shared__ float As[128 * 20];    // [m][k] stride 20 (conflict-free LDSM)
    __shared__ float Bt[128 * 20];    // [n][k] stride 20 (transposed W tile)

    const int bm = blockIdx.y, bn = blockIdx.x;
    const int tid = threadIdx.x;
    const int wid = tid >> 5, lane = tid & 31;
    const int wm = wid >> 2, wn = wid & 3;          // 2 x 4 warp grid
    const int q = lane & 3, r = lane >> 2;

    float acc[4][4][4];
#pragma unroll
    for (int i = 0; i < 4; ++i)
#pragma unroll
        for (int j = 0; j < 4; ++j)
#pragma unroll
            for (int k = 0; k < 4; ++k) acc[i][j][k] = 0.f;

    // LDSM source addresses (fixed per thread, advance by kstep offset)
    const int a_row = wm * 64 + (lane & 15);
    const int a_col = (lane >> 4) << 2;
    const int b_row_base = wn * 32 + (lane & 7) + ((lane & 16) ? 8 : 0);
    const int b_col = (lane & 8) ? 4 : 0;

    for (int k0 = 0; k0 < C_; k0 += 16) {
        // Stage A tile (128 x 16), cvt to tf32
#pragma unroll
        for (int i = 0; i < 2; ++i) {
            int f = tid + i * 256;
            int row = f >> 2, kc = (f & 3) << 2;
            float4 v = *(const float4*)(x + (size_t)(bm * 128 + row) * C_ + k0 + kc);
            uint4 u = {f2tf(v.x), f2tf(v.y), f2tf(v.z), f2tf(v.w)};
            *(uint4*)&As[row * 20 + kc] = u;
        }
        // Stage B tile (16 x 128) transposed to [n][k], cvt to tf32
#pragma unroll
        for (int i = 0; i < 2; ++i) {
            int f = tid + i * 256;
            int kr = f >> 5, c4 = (f & 31) << 2;
            float4 v = *(const float4*)(W + (size_t)(k0 + kr) * TC3 + bn * 128 + c4);
            Bt[(c4 + 0) * 20 + kr] = __uint_as_float(f2tf(v.x));
            Bt[(c4 + 1) * 20 + kr] = __uint_as_float(f2tf(v.y));
            Bt[(c4 + 2) * 20 + kr] = __uint_as_float(f2tf(v.z));
            Bt[(c4 + 3) * 20 + kr] = __uint_as_float(f2tf(v.w));
        }
        __syncthreads();

#pragma unroll
        for (int ks = 0; ks < 2; ++ks) {
            uint32_t af[4][4];
#pragma unroll
            for (int mt = 0; mt < 4; ++mt)
                ldsm4(af[mt][0], af[mt][1], af[mt][2], af[mt][3],
                      sptr(&As[(a_row + mt * 16) * 20 + ks * 8 + a_col]));
            uint32_t bf[4][2];
#pragma unroll
            for (int np = 0; np < 2; ++np) {
                uint32_t r0, r1, r2, r3;
                ldsm4(r0, r1, r2, r3,
                      sptr(&Bt[(b_row_base + np * 16) * 20 + ks * 8 + b_col]));
                bf[np * 2][0] = r0;     bf[np * 2][1] = r1;
                bf[np * 2 + 1][0] = r2; bf[np * 2 + 1][1] = r3;
            }
#pragma unroll
            for (int mt = 0; mt < 4; ++mt)
#pragma unroll
                for (int nt = 0; nt < 4; ++nt)
                    mma_tf32(acc[mt][nt], af[mt], bf[nt]);
        }
        __syncthreads();
    }

    // Epilogue: bias + scatter. `which` is uniform per CTA (BN=128 divides 1024)
    const int which = (bn * 128) >> 10;
    float* dst = (which == 0) ? g_q : (which == 1) ? g_k : g_v;
#pragma unroll
    for (int mt = 0; mt < 4; ++mt) {
#pragma unroll
        for (int half = 0; half < 2; ++half) {
            int m = bm * 128 + wm * 64 + mt * 16 + r + half * 8;
            int bb = m >> 11, tt = m & 2047;
#pragma unroll
            for (int nt = 0; nt < 4; ++nt) {
                int n = bn * 128 + wn * 32 + nt * 8 + 2 * q;
                int cc = n & 1023;
                int hh = cc >> 6, dd = cc & 63;
                float2 bv = *(const float2*)(bias + n);
                float2 o;
                o.x = acc[mt][nt][half * 2 + 0] + bv.x;
                o.y = acc[mt][nt][half * 2 + 1] + bv.y;
                *(float2*)(dst + ((size_t)(bb * H_ + hh) * T_ + tt) * D_ + dd) = o;
            }
        }
    }
}

// ---------------------------------------------------------------------------
// Kernel 2: flash attention with tf32 mma. CTA = (b, h, 128 q-rows), 8 warps,
// each warp owns 16 q-rows. Online softmax over 64-key blocks.
// ---------------------------------------------------------------------------
static constexpr int QS_STRIDE = 68;
static constexpr int AT_SMEM_BYTES =
    (128 * QS_STRIDE + 64 * QS_STRIDE + 64 * QS_STRIDE) * 4 + 64 * 4;

__global__ __launch_bounds__(256) void attn_kernel(
    const int* __restrict__ mask,     // (B_, T_)
    float* __restrict__ out)
{
    extern __shared__ float sm[];
    float* Qs = sm;                       // [128][68]  (aliased as Ps after Q-frag load)
    float* Ps = sm;
    float* Ks = sm + 128 * QS_STRIDE;     // [krow][d]  [64][68]
    float* Vt = Ks + 64 * QS_STRIDE;      // [d][krow]  [64][68] (transposed)
    int*   mk = (int*)(Vt + 64 * QS_STRIDE);

    const int qb = blockIdx.x, h = blockIdx.y, b = blockIdx.z;
    const int tid = threadIdx.x;
    const int wid = tid >> 5, lane = tid & 31;
    const int q = lane & 3, r = lane >> 2;
    const int qr = wid * 16;              // warp's q-row base within tile

    const size_t bh = (size_t)(b * H_ + h);
    const float* qptr  = g_q + (bh * T_ + (size_t)qb * 128) * D_;
    const float* kbase = g_k + bh * T_ * D_;
    const float* vbase = g_v + bh * T_ * D_;
    const int*   mbase = mask + (size_t)b * T_;

    // Stage Q (128 x 64) as tf32
#pragma unroll
    for (int i = 0; i < 8; ++i) {
        int f = tid + i * 256;
        int row = f >> 4, c4 = (f & 15) << 2;
        float4 v = *(const float4*)(qptr + (size_t)row * D_ + c4);
        uint4 u = {f2tf(v.x), f2tf(v.y), f2tf(v.z), f2tf(v.w)};
        *(uint4*)&Qs[row * QS_STRIDE + c4] = u;
    }
    __syncthreads();

    // Q fragments: register-resident for all 32 K-blocks
    uint32_t qf[8][4];
    const int a_row = qr + (lane & 15);
    const int a_col = (lane >> 4) << 2;
#pragma unroll
    for (int ks = 0; ks < 8; ++ks)
        ldsm4(qf[ks][0], qf[ks][1], qf[ks][2], qf[ks][3],
              sptr(&Qs[a_row * QS_STRIDE + ks * 8 + a_col]));

    float oacc[8][4];
#pragma unroll
    for (int i = 0; i < 8; ++i)
#pragma unroll
        for (int j = 0; j < 4; ++j) oacc[i][j] = 0.f;
    float m0 = -1e30f, m1 = -1e30f, l0 = 0.f, l1 = 0.f;
    const float scale = 0.125f;

    const int b_row = (lane & 7) + ((lane & 16) ? 8 : 0);
    const int b_col = (lane & 8) ? 4 : 0;

    for (int kb = 0; kb < T_ / 64; ++kb) {
        const float* kptr = kbase + (size_t)kb * 64 * D_;
        const float* vptr = vbase + (size_t)kb * 64 * D_;
        // Stage K [krow][d] and V transposed [d][krow], cvt tf32
#pragma unroll
        for (int i = 0; i < 4; ++i) {
            int f = tid + i * 256;
            int row = f >> 4, c4 = (f & 15) << 2;
            float4 v = *(const float4*)(kptr + (size_t)row * D_ + c4);
            uint4 u = {f2tf(v.x), f2tf(v.y), f2tf(v.z), f2tf(v.w)};
            *(uint4*)&Ks[row * QS_STRIDE + c4] = u;
        }
#pragma unroll
        for (int i = 0; i < 4; ++i) {
            int f = tid + i * 256;
            int row = f >> 4, c4 = (f & 15) << 2;
            float4 v = *(const float4*)(vptr + (size_t)row * D_ + c4);
            Vt[(c4 + 0) * QS_STRIDE + row] = __uint_as_float(f2tf(v.x));
            Vt[(c4 + 1) * QS_STRIDE + row] = __uint_as_float(f2tf(v.y));
            Vt[(c4 + 2) * QS_STRIDE + row] = __uint_as_float(f2tf(v.z));
            Vt[(c4 + 3) * QS_STRIDE + row] = __uint_as_float(f2tf(v.w));
        }
        if (tid < 64) mk[tid] = mbase[kb * 64 + tid];
        __syncthreads();

        // S = Q . K^T (warp: 16 x 64)
        float sacc[8][4];
#pragma unroll
        for (int i = 0; i < 8; ++i)
#pragma unroll
            for (int j = 0; j < 4; ++j) sacc[i][j] = 0.f;

#pragma unroll
        for (int ks = 0; ks < 8; ++ks) {
            uint32_t kf[8][2];
#pragma unroll
            for (int np = 0; np < 4; ++np) {
                uint32_t r0, r1, r2, r3;
                ldsm4(r0, r1, r2, r3,
                      sptr(&Ks[(np * 16 + b_row) * QS_STRIDE + ks * 8 + b_col]));
                kf[np * 2][0] = r0;     kf[np * 2][1] = r1;
                kf[np * 2 + 1][0] = r2; kf[np * 2 + 1][1] = r3;
            }
#pragma unroll
            for (int nt = 0; nt < 8; ++nt)
                mma_tf32(sacc[nt], qf[ks], kf[nt]);
        }

        // mask + scale, row max (rows r and r+8 of this warp's 16)
        float rm0 = -1e30f, rm1 = -1e30f;
#pragma unroll
        for (int nt = 0; nt < 8; ++nt) {
            int c = nt * 8 + 2 * q;
            bool ma = mk[c] != 0, mb = mk[c + 1] != 0;
            sacc[nt][0] = ma ? sacc[nt][0] * scale : -1e30f;
            sacc[nt][1] = mb ? sacc[nt][1] * scale : -1e30f;
            sacc[nt][2] = ma ? sacc[nt][2] * scale : -1e30f;
            sacc[nt][3] = mb ? sacc[nt][3] * scale : -1e30f;
            rm0 = fmaxf(rm0, fmaxf(sacc[nt][0], sacc[nt][1]));
            rm1 = fmaxf(rm1, fmaxf(sacc[nt][2], sacc[nt][3]));
        }
#pragma unroll
        for (int st = 1; st < 4; st <<= 1) {
            rm0 = fmaxf(rm0, __shfl_xor_sync(0xffffffffu, rm0, st));
            rm1 = fmaxf(rm1, __shfl_xor_sync(0xffffffffu, rm1, st));
        }
        float mn0 = fmaxf(m0, rm0), mn1 = fmaxf(m1, rm1);
        float cr0 = __expf(m0 - mn0), cr1 = __expf(m1 - mn1);
        m0 = mn0; m1 = mn1;

        float rs0 = 0.f, rs1 = 0.f;
#pragma unroll
        for (int nt = 0; nt < 8; ++nt) {
            float e0 = __expf(sacc[nt][0] - mn0);
            float e1 = __expf(sacc[nt][1] - mn0);
            float e2 = __expf(sacc[nt][2] - mn1);
            float e3 = __expf(sacc[nt][3] - mn1);
            rs0 += e0 + e1; rs1 += e2 + e3;
            uint2 p01 = {f2tf(e0), f2tf(e1)};
            uint2 p23 = {f2tf(e2), f2tf(e3)};
            *(uint2*)&Ps[(qr + r) * QS_STRIDE + nt * 8 + 2 * q] = p01;
            *(uint2*)&Ps[(qr + r + 8) * QS_STRIDE + nt * 8 + 2 * q] = p23;
        }
#pragma unroll
        for (int st = 1; st < 4; st <<= 1) {
            rs0 += __shfl_xor_sync(0xffffffffu, rs0, st);
            rs1 += __shfl_xor_sync(0xffffffffu, rs1, st);
        }
        l0 = l0 * cr0 + rs0;
        l1 = l1 * cr1 + rs1;
#pragma unroll
        for (int nt = 0; nt < 8; ++nt) {
            oacc[nt][0] *= cr0; oacc[nt][1] *= cr0;
            oacc[nt][2] *= cr1; oacc[nt][3] *= cr1;
        }
        __syncwarp();

        // O += P . V (warp rows only; P read back as A-fragments)
#pragma unroll
        for (int ks = 0; ks < 8; ++ks) {
            uint32_t pf[4];
            ldsm4(pf[0], pf[1], pf[2], pf[3],
                  sptr(&Ps[a_row * QS_STRIDE + ks * 8 + a_col]));
            uint32_t vf[8][2];
#pragma unroll
            for (int np = 0; np < 4; ++np) {
                uint32_t r0, r1, r2, r3;
                ldsm4(r0, r1, r2, r3,
                      sptr(&Vt[(np * 16 + b_row) * QS_STRIDE + ks * 8 + b_col]));
                vf[np * 2][0] = r0;     vf[np * 2][1] = r1;
                vf[np * 2 + 1][0] = r2; vf[np * 2 + 1][1] = r3;
            }
#pragma unroll
            for (int nt = 0; nt < 8; ++nt)
                mma_tf32(oacc[nt], pf, vf[nt]);
        }
        __syncthreads();
    }

    // Normalize + write. out = b*T*C + h*T*D + t*D + d
    float inv0 = (l0 > 0.f) ? 1.f / l0 : 0.f;
    float inv1 = (l1 > 0.f) ? 1.f / l1 : 0.f;
    float* obase = out + (size_t)b * T_ * C_ + (size_t)h * T_ * D_;
    int row0 = qb * 128 + qr + r;
#pragma unroll
    for (int nt = 0; nt < 8; ++nt) {
        int dd = nt * 8 + 2 * q;
        float2 v0 = {oacc[nt][0] * inv0, oacc[nt][1] * inv0};
        float2 v1 = {oacc[nt][2] * inv1, oacc[nt][3] * inv1};
        *(float2*)(obase + (size_t)row0 * D_ + dd) = v0;
        *(float2*)(obase + (size_t)(row0 + 8) * D_ + dd) = v1;
    }
}

// ---------------------------------------------------------------------------
extern "C" void kernel_launch(void* const* d_in, const int* in_sizes, int n_in,
                              void* d_out, int out_size) {
    (void)in_sizes; (void)n_in; (void)out_size;
    const float* x    = (const float*)d_in[0];
    const int*   mask = (const int*)d_in[1];
    const float* W    = (const float*)d_in[2];
    const float* bias = (const float*)d_in[3];
    float*       out  = (float*)d_out;

    static int _attr_once = []() {
        cudaFuncSetAttribute(attn_kernel,
                             cudaFuncAttributeMaxDynamicSharedMemorySize,
                             AT_SMEM_BYTES);
        return 0;
    }();
    (void)_attr_once;

    dim3 g1(TC3 / 128, M_ / 128);   // (24, 128)
    qkv_gemm_kernel<<<g1, 256>>>(x, W, bias);

    dim3 g2(T_ / 128, H_, B_);      // (16, 16, 8)
    attn_kernel<<<g2, 256, AT_SMEM_BYTES>>>(mask, out);
}